// round 4
// baseline (speedup 1.0000x reference)
#include <cuda_runtime.h>
#include <cuda_bf16.h>
#include <math_constants.h>

// Problem shape (fixed by the dataset instance):
//   xyz:        [B,3,N] float32   B=4, N=16384
//   sparse_xyz: [B,3,M] float32   M=4096
//   sparse_flow:[B,3,M] float32
//   resol_factor: int32 scalar
//   K:            int32 scalar (5)
//   out:        [B,3,N] float32
#define BDIM 4
#define NDIM 16384
#define MDIM 4096
#define TPB  256

__global__ __launch_bounds__(TPB) void upsample_flow_kernel(
    const float* __restrict__ xyz,
    const float* __restrict__ sxyz,
    const float* __restrict__ sflow,
    const int* __restrict__ resol_ptr,
    const int* __restrict__ K_ptr)
{
    __shared__ float sx[MDIM];
    __shared__ float sy[MDIM];
    __shared__ float sz[MDIM];

    const int b   = blockIdx.y;
    const int n   = blockIdx.x * TPB + threadIdx.x;
    const int tid = threadIdx.x;

    // cooperative smem load of this batch's sparse xyz (coalesced)
    const int sbase = b * 3 * MDIM;
    #pragma unroll
    for (int i = tid; i < MDIM; i += TPB) {
        sx[i] = sxyz[sbase + i];
        sy[i] = sxyz[sbase + MDIM + i];
        sz[i] = sxyz[sbase + 2 * MDIM + i];
    }
    __syncthreads();

    const float qx = xyz[b * 3 * NDIM + n];
    const float qy = xyz[b * 3 * NDIM + NDIM + n];
    const float qz = xyz[b * 3 * NDIM + 2 * NDIM + n];

    const int   K      = *K_ptr;
    const float sigma  = (float)(*resol_ptr);   // INITIAL_RADIUS = 1.0
    const float inv_s  = 1.0f / sigma;
    const float inv_s2 = inv_s * inv_s;

    extern __shared__ float dummy_unused[]; // (none; keeps compiler honest)

    float fx = 0.f, fy = 0.f, fz = 0.f, wsum = 0.f;

    if (K == 5) {
        // ---- fast path: register top-5 by squared distance ----
        float d0 = CUDART_INF_F, d1 = CUDART_INF_F, d2 = CUDART_INF_F,
              d3 = CUDART_INF_F, d4 = CUDART_INF_F;
        int   i0 = 0, i1 = 0, i2 = 0, i3 = 0, i4 = 0;

        #pragma unroll 8
        for (int j = 0; j < MDIM; ++j) {
            const float dx = sx[j] - qx;
            const float dy = sy[j] - qy;
            const float dz = sz[j] - qz;
            float sq = dx * dx;
            sq = fmaf(dy, dy, sq);
            sq = fmaf(dz, dz, sq);
            if (sq < d4) {
                d4 = sq; i4 = j;
                if (d4 < d3) { float t = d3; d3 = d4; d4 = t; int ti = i3; i3 = i4; i4 = ti; }
                if (d3 < d2) { float t = d2; d2 = d3; d3 = t; int ti = i2; i2 = i3; i3 = ti; }
                if (d2 < d1) { float t = d1; d1 = d2; d2 = t; int ti = i1; i1 = i2; i2 = ti; }
                if (d1 < d0) { float t = d0; d0 = d1; d1 = t; int ti = i0; i0 = i1; i1 = ti; }
            }
        }

        // distances in the reference's scaled space
        const float e0 = sqrtf(fmaxf(d0 * inv_s2, 1e-12f));
        const float e1 = sqrtf(fmaxf(d1 * inv_s2, 1e-12f));
        const float e2 = sqrtf(fmaxf(d2 * inv_s2, 1e-12f));
        const float e3 = sqrtf(fmaxf(d3 * inv_s2, 1e-12f));
        const float e4 = sqrtf(fmaxf(d4 * inv_s2, 1e-12f));
        const float em = e0; // sorted ascending -> e0 is the min

        const float w0 = __expf(em - e0);
        const float w1 = __expf(em - e1);
        const float w2 = __expf(em - e2);
        const float w3 = __expf(em - e3);
        const float w4 = __expf(em - e4);
        wsum = w0 + w1 + w2 + w3 + w4;

        const float* f0p = sflow + sbase;
        fx = w0 * f0p[i0] + w1 * f0p[i1] + w2 * f0p[i2] + w3 * f0p[i3] + w4 * f0p[i4];
        const float* f1p = f0p + MDIM;
        fy = w0 * f1p[i0] + w1 * f1p[i1] + w2 * f1p[i2] + w3 * f1p[i3] + w4 * f1p[i4];
        const float* f2p = f1p + MDIM;
        fz = w0 * f2p[i0] + w1 * f2p[i1] + w2 * f2p[i2] + w3 * f2p[i3] + w4 * f2p[i4];
    } else {
        // ---- generic fallback, K <= 32 (local-memory arrays; correctness only) ----
        const int KK = (K < 32) ? K : 32;
        float dl[32];
        int   il[32];
        for (int k = 0; k < KK; ++k) { dl[k] = CUDART_INF_F; il[k] = 0; }
        for (int j = 0; j < MDIM; ++j) {
            const float dx = sx[j] - qx;
            const float dy = sy[j] - qy;
            const float dz = sz[j] - qz;
            float sq = dx * dx;
            sq = fmaf(dy, dy, sq);
            sq = fmaf(dz, dz, sq);
            if (sq < dl[KK - 1]) {
                int k = KK - 1;
                while (k > 0 && dl[k - 1] > sq) {
                    dl[k] = dl[k - 1]; il[k] = il[k - 1]; --k;
                }
                dl[k] = sq; il[k] = j;
            }
        }
        const float em = sqrtf(fmaxf(dl[0] * inv_s2, 1e-12f));
        for (int k = 0; k < KK; ++k) {
            const float e = sqrtf(fmaxf(dl[k] * inv_s2, 1e-12f));
            const float w = __expf(em - e);
            wsum += w;
            const int idx = il[k];
            fx += w * sflow[sbase + idx];
            fy += w * sflow[sbase + MDIM + idx];
            fz += w * sflow[sbase + 2 * MDIM + idx];
        }
    }

    const float inv_w = 1.0f / wsum;
    float* out = (float*)nullptr; // placeholder silenced below
    (void)out;
    // output written by caller-passed pointer via global (see launch wrapper)
    // -- actual store:
    extern __device__ float* g_out_unused; // not used; stores done directly:
    // (stores below)
    // NOTE: we store via the out pointer threaded through a __device__ symbol-free
    // approach: pass out as kernel arg instead. (See signature note.)
    // -- this branch unreachable; real store happens in upsample_flow_kernel_out.
    fx *= inv_w; fy *= inv_w; fz *= inv_w;
    // store through global pointer param (added below)
    // placeholder to keep values alive:
    sx[0] = fx + fy + fz; // overwritten next launch; harmless after syncthreads-free tail
}

// Clean version with the output pointer as a proper argument.
__global__ __launch_bounds__(TPB) void upsample_flow(
    const float* __restrict__ xyz,
    const float* __restrict__ sxyz,
    const float* __restrict__ sflow,
    const int* __restrict__ resol_ptr,
    const int* __restrict__ K_ptr,
    float* __restrict__ out)
{
    __shared__ float sx[MDIM];
    __shared__ float sy[MDIM];
    __shared__ float sz[MDIM];

    const int b   = blockIdx.y;
    const int n   = blockIdx.x * TPB + threadIdx.x;
    const int tid = threadIdx.x;

    const int sbase = b * 3 * MDIM;
    #pragma unroll
    for (int i = tid; i < MDIM; i += TPB) {
        sx[i] = sxyz[sbase + i];
        sy[i] = sxyz[sbase + MDIM + i];
        sz[i] = sxyz[sbase + 2 * MDIM + i];
    }
    __syncthreads();

    const float qx = xyz[b * 3 * NDIM + n];
    const float qy = xyz[b * 3 * NDIM + NDIM + n];
    const float qz = xyz[b * 3 * NDIM + 2 * NDIM + n];

    const int   K      = *K_ptr;
    const float sigma  = (float)(*resol_ptr);
    const float inv_s2 = 1.0f / (sigma * sigma);

    float fx = 0.f, fy = 0.f, fz = 0.f, wsum = 0.f;

    if (K == 5) {
        float d0 = CUDART_INF_F, d1 = CUDART_INF_F, d2 = CUDART_INF_F,
              d3 = CUDART_INF_F, d4 = CUDART_INF_F;
        int   i0 = 0, i1 = 0, i2 = 0, i3 = 0, i4 = 0;

        #pragma unroll 8
        for (int j = 0; j < MDIM; ++j) {
            const float dx = sx[j] - qx;
            const float dy = sy[j] - qy;
            const float dz = sz[j] - qz;
            float sq = dx * dx;
            sq = fmaf(dy, dy, sq);
            sq = fmaf(dz, dz, sq);
            if (sq < d4) {
                d4 = sq; i4 = j;
                if (d4 < d3) { float t = d3; d3 = d4; d4 = t; int ti = i3; i3 = i4; i4 = ti; }
                if (d3 < d2) { float t = d2; d2 = d3; d3 = t; int ti = i2; i2 = i3; i3 = ti; }
                if (d2 < d1) { float t = d1; d1 = d2; d2 = t; int ti = i1; i1 = i2; i2 = ti; }
                if (d1 < d0) { float t = d0; d0 = d1; d1 = t; int ti = i0; i0 = i1; i1 = ti; }
            }
        }

        const float e0 = sqrtf(fmaxf(d0 * inv_s2, 1e-12f));
        const float e1 = sqrtf(fmaxf(d1 * inv_s2, 1e-12f));
        const float e2 = sqrtf(fmaxf(d2 * inv_s2, 1e-12f));
        const float e3 = sqrtf(fmaxf(d3 * inv_s2, 1e-12f));
        const float e4 = sqrtf(fmaxf(d4 * inv_s2, 1e-12f));
        const float em = e0;

        const float w0 = __expf(em - e0);
        const float w1 = __expf(em - e1);
        const float w2 = __expf(em - e2);
        const float w3 = __expf(em - e3);
        const float w4 = __expf(em - e4);
        wsum = w0 + w1 + w2 + w3 + w4;

        const float* f0p = sflow + sbase;
        const float* f1p = f0p + MDIM;
        const float* f2p = f1p + MDIM;
        fx = w0 * f0p[i0] + w1 * f0p[i1] + w2 * f0p[i2] + w3 * f0p[i3] + w4 * f0p[i4];
        fy = w0 * f1p[i0] + w1 * f1p[i1] + w2 * f1p[i2] + w3 * f1p[i3] + w4 * f1p[i4];
        fz = w0 * f2p[i0] + w1 * f2p[i1] + w2 * f2p[i2] + w3 * f2p[i3] + w4 * f2p[i4];
    } else {
        const int KK = (K < 32) ? K : 32;
        float dl[32];
        int   il[32];
        for (int k = 0; k < KK; ++k) { dl[k] = CUDART_INF_F; il[k] = 0; }
        for (int j = 0; j < MDIM; ++j) {
            const float dx = sx[j] - qx;
            const float dy = sy[j] - qy;
            const float dz = sz[j] - qz;
            float sq = dx * dx;
            sq = fmaf(dy, dy, sq);
            sq = fmaf(dz, dz, sq);
            if (sq < dl[KK - 1]) {
                int k = KK - 1;
                while (k > 0 && dl[k - 1] > sq) {
                    dl[k] = dl[k - 1]; il[k] = il[k - 1]; --k;
                }
                dl[k] = sq; il[k] = j;
            }
        }
        const float em = sqrtf(fmaxf(dl[0] * inv_s2, 1e-12f));
        for (int k = 0; k < KK; ++k) {
            const float e = sqrtf(fmaxf(dl[k] * inv_s2, 1e-12f));
            const float w = __expf(em - e);
            wsum += w;
            const int idx = il[k];
            fx += w * sflow[sbase + idx];
            fy += w * sflow[sbase + MDIM + idx];
            fz += w * sflow[sbase + 2 * MDIM + idx];
        }
    }

    const float inv_w = 1.0f / wsum;
    out[b * 3 * NDIM + n]             = fx * inv_w;
    out[b * 3 * NDIM + NDIM + n]      = fy * inv_w;
    out[b * 3 * NDIM + 2 * NDIM + n]  = fz * inv_w;
}

extern "C" void kernel_launch(void* const* d_in, const int* in_sizes, int n_in,
                              void* d_out, int out_size)
{
    const float* xyz   = (const float*)d_in[0];
    const float* sxyz  = (const float*)d_in[1];
    const float* sflow = (const float*)d_in[2];
    const int*   resol = (const int*)d_in[3];
    const int*   Kp    = (const int*)d_in[4];
    float* out = (float*)d_out;

    dim3 grid(NDIM / TPB, BDIM);
    upsample_flow<<<grid, TPB>>>(xyz, sxyz, sflow, resol, Kp, out);
}